// round 13
// baseline (speedup 1.0000x reference)
#include <cuda_runtime.h>
#include <cuda_bf16.h>
#include <math.h>
#include <stdint.h>

typedef unsigned long long ull;

#define NN_MAX 50000
#define NE_MAX 1000000

// ---- device-global scratch (no allocations allowed) ----
__device__ float g_s[NN_MAX];
__device__ float g_v[NN_MAX * 6];
__device__ float g_vus[NN_MAX * 8];
__device__ float g_agg[NN_MAX * 12];     // pre-contracted: sd[3] + vd[6], pad 12
__device__ float g_nhat[NE_MAX * 4];
__device__ float g_radial[NE_MAX * 8];
__device__ float g_mix[NE_MAX * 8];

#define INV_SQRT2 0.70710678118654752f
#define INV_SQRT3 0.57735026918962576f
#define INV_SQRT5 0.44721359549995794f
#define INV_SQRT8 0.35355339059327376f
#define SQRT2_F   1.4142135623730951f
#define C121_F    2.1213203435596424f
#define SQRT3_F   1.7320508075688772f

// swish via HW tanh: swish(x) = 0.5x + 0.5x*tanh(0.5x)
__device__ __forceinline__ float swishf(float x) {
    float hx = 0.5f * x;
    float t;
    asm("tanh.approx.f32 %0, %1;" : "=f"(t) : "f"(hx));
    return fmaf(hx, t, hx);
}
__device__ __forceinline__ float swish_exact(float x) {
    return __fdividef(x, 1.0f + __expf(-x));
}

// ---- bf16 2-way split, packed pair (x -> low half, y -> high half) ----
__device__ __forceinline__ void bfsplit2(float x, float y,
                                         uint32_t& hp, uint32_t& lp) {
    uint32_t h;
    asm("cvt.rn.bf16x2.f32 %0, %1, %2;" : "=r"(h) : "f"(y), "f"(x));
    float xh = __uint_as_float(h << 16);
    float yh = __uint_as_float(h & 0xFFFF0000u);
    float xr = x - xh;
    float yr = y - yh;
    uint32_t l;
    asm("cvt.rn.bf16x2.f32 %0, %1, %2;" : "=r"(l) : "f"(yr), "f"(xr));
    hp = h;
    lp = l;
}

// ---- warp MMA: bf16 m16n8k16 ----
__device__ __forceinline__ void mma16(float d[4], const uint32_t a[4],
                                      uint32_t b0, uint32_t b1) {
    asm volatile(
        "mma.sync.aligned.m16n8k16.row.col.f32.bf16.bf16.f32 "
        "{%0,%1,%2,%3}, {%4,%5,%6,%7}, {%8,%9}, {%0,%1,%2,%3};"
        : "+f"(d[0]), "+f"(d[1]), "+f"(d[2]), "+f"(d[3])
        : "r"(a[0]), "r"(a[1]), "r"(a[2]), "r"(a[3]), "r"(b0), "r"(b1));
}

// ---------------------------------------------------------------------------
// init node state
// ---------------------------------------------------------------------------
__global__ void k_init(const float* __restrict__ nf, int nn) {
    int n = blockIdx.x * blockDim.x + threadIdx.x;
    if (n >= nn) return;
    g_s[n] = nf[n * 7];
#pragma unroll
    for (int i = 0; i < 6; i++) g_v[n * 6 + i] = nf[n * 7 + 1 + i];
}

// ---------------------------------------------------------------------------
// per-edge geometry
// ---------------------------------------------------------------------------
__global__ void k_geom(const float* __restrict__ pos,
                       const int* __restrict__ snd,
                       const int* __restrict__ rcv, int ne) {
    int e = blockIdx.x * blockDim.x + threadIdx.x;
    if (e >= ne) return;
    int s = snd[e], r = rcv[e];
    float vx = pos[r * 3 + 0] - pos[s * 3 + 0];
    float vy = pos[r * 3 + 1] - pos[s * 3 + 1];
    float vz = pos[r * 3 + 2] - pos[s * 3 + 2];
    float len = sqrtf(vx * vx + vy * vy + vz * vz);
    float inv = (len == 0.0f) ? 1.0f : (1.0f / len);
    *(float4*)&g_nhat[e * 4] = make_float4(vx * inv, vy * inv, vz * inv, 0.0f);

    float env = 0.0f;
    if (len < 1.0f) {
        float x = len;
        float x2 = x * x, x3 = x2 * x;
        float x6 = x3 * x3, x7 = x6 * x, x8 = x7 * x;
        env = 1.0f - 28.0f * x6 + 48.0f * x7 - 21.0f * x8;
    }
    float coef = (len == 0.0f) ? 0.0f : (SQRT2_F * env * inv);

    float s1, c1;
    sincospif(len, &s1, &c1);
    float out[8];
    float sm1 = 0.0f, sk = s1;
#pragma unroll
    for (int k = 0; k < 8; k++) {
        out[k] = sk * coef;
        float nx = 2.0f * c1 * sk - sm1;
        sm1 = sk; sk = nx;
    }
    *(float4*)&g_radial[e * 8]     = make_float4(out[0], out[1], out[2], out[3]);
    *(float4*)&g_radial[e * 8 + 4] = make_float4(out[4], out[5], out[6], out[7]);
}

// ---------------------------------------------------------------------------
// radial MLP: all phases bf16 m16n8k16.
// Phase 1 (K=8): A k16 = [r_hi | r_lo], B = [w_hi|w_hi] then [w_lo|w_lo]
//   -> 2 mma/j-tile, full double-bf16 product (all 4 cross terms).
// Phases 2-3 (K=64): 2-way bf16 split, 3 product terms.
// k16 A-frag == concat of two adjacent N=8 D-frags -> no shuffles.
// ---------------------------------------------------------------------------
__global__ __launch_bounds__(128)
void k_mix_mma(const float* __restrict__ W1, const float* __restrict__ W2,
               const float* __restrict__ W3, int ne, int ntiles) {
    __shared__ uint32_t sW1h[8 * 32], sW1l[8 * 32];   // W1 bf16 dup packs
    __shared__ ull sB2h[32 * 32], sB2l[32 * 32];      // W2 bf16 packs
    __shared__ ull sB3h[4 * 32],  sB3l[4 * 32];       // W3 bf16 packs

    int tid = threadIdx.x;

    // ---- prepack W1 (scale 1/sqrt8 folded): lane(g,t4) -> k=2t4,2t4+1; col=8j+g
    for (int idx = tid; idx < 256; idx += 128) {
        int j = idx >> 5, l = idx & 31;
        int g = l >> 2, t4 = l & 3;
        int col = 8 * j + g;
        float w0 = W1[(2 * t4) * 64 + col] * INV_SQRT8;
        float w1 = W1[(2 * t4 + 1) * 64 + col] * INV_SQRT8;
        uint32_t h, lo;
        bfsplit2(w0, w1, h, lo);
        sW1h[idx] = h;
        sW1l[idx] = lo;
    }
    // ---- prepack W2 (scale 0.125 folded) ----
    for (int idx = tid; idx < 1024; idx += 128) {
        int t = idx >> 5, l = idx & 31;
        int kk = t >> 3, j = t & 7;
        int g = l >> 2, t4 = l & 3;
        int col = 8 * j + g;
        int r0 = 16 * kk + 2 * t4;
        float w00 = W2[(r0 + 0) * 64 + col] * 0.125f;
        float w01 = W2[(r0 + 1) * 64 + col] * 0.125f;
        float w10 = W2[(r0 + 8) * 64 + col] * 0.125f;
        float w11 = W2[(r0 + 9) * 64 + col] * 0.125f;
        uint32_t b0h, b0l, b1h, b1l;
        bfsplit2(w00, w01, b0h, b0l);
        bfsplit2(w10, w11, b1h, b1l);
        sB2h[idx] = ((ull)b1h << 32) | b0h;
        sB2l[idx] = ((ull)b1l << 32) | b0l;
    }
    // ---- prepack W3 (scale 0.125 folded) ----
    for (int idx = tid; idx < 128; idx += 128) {
        int kk = idx >> 5, l = idx & 31;
        int g = l >> 2, t4 = l & 3;
        int r0 = 16 * kk + 2 * t4;
        float w00 = W3[(r0 + 0) * 8 + g] * 0.125f;
        float w01 = W3[(r0 + 1) * 8 + g] * 0.125f;
        float w10 = W3[(r0 + 8) * 8 + g] * 0.125f;
        float w11 = W3[(r0 + 9) * 8 + g] * 0.125f;
        uint32_t b0h, b0l, b1h, b1l;
        bfsplit2(w00, w01, b0h, b0l);
        bfsplit2(w10, w11, b1h, b1l);
        sB3h[idx] = ((ull)b1h << 32) | b0h;
        sB3l[idx] = ((ull)b1l << 32) | b0l;
    }
    __syncthreads();

    int w    = tid >> 5;
    int lane = tid & 31;
    int g    = lane >> 2;
    int t4   = lane & 3;

    for (int tile = blockIdx.x; tile < ntiles; tile += gridDim.x) {
        int base = tile * 64 + w * 16;
        int eg  = base + g;      if (eg  >= ne) eg  = ne - 1;
        int eg8 = base + g + 8;  if (eg8 >= ne) eg8 = ne - 1;

        // ===== phase 1 (bf16 packed K): h1 = swish(radial @ W1s) =====
        uint32_t a1[4];
        {
            float2 ra = *(const float2*)&g_radial[eg  * 8 + 2 * t4];
            float2 rb = *(const float2*)&g_radial[eg8 * 8 + 2 * t4];
            uint32_t hp0, lp0, hp1, lp1;
            bfsplit2(ra.x, ra.y, hp0, lp0);
            bfsplit2(rb.x, rb.y, hp1, lp1);
            a1[0] = hp0; a1[1] = hp1; a1[2] = lp0; a1[3] = lp1;
        }
        float hj[8][4];
#pragma unroll
        for (int j = 0; j < 8; j++) {
            float D[4] = {0.f, 0.f, 0.f, 0.f};
            uint32_t bh = sW1h[j * 32 + lane];
            uint32_t bl = sW1l[j * 32 + lane];
            mma16(D, a1, bh, bh);
            mma16(D, a1, bl, bl);
            hj[j][0] = swishf(D[0]);
            hj[j][1] = swishf(D[1]);
            hj[j][2] = swishf(D[2]);
            hj[j][3] = swishf(D[3]);
        }

        // ===== phase 2 (bf16 k16): h2 = swish(h1 @ W2s) =====
        float D2[8][4];
#pragma unroll
        for (int j = 0; j < 8; j++)
#pragma unroll
            for (int q = 0; q < 4; q++) D2[j][q] = 0.f;

#pragma unroll
        for (int kk = 0; kk < 4; kk++) {
            uint32_t a2h[4], a2l[4];
            bfsplit2(hj[2 * kk][0],     hj[2 * kk][1],     a2h[0], a2l[0]);
            bfsplit2(hj[2 * kk][2],     hj[2 * kk][3],     a2h[1], a2l[1]);
            bfsplit2(hj[2 * kk + 1][0], hj[2 * kk + 1][1], a2h[2], a2l[2]);
            bfsplit2(hj[2 * kk + 1][2], hj[2 * kk + 1][3], a2h[3], a2l[3]);
#pragma unroll
            for (int j = 0; j < 8; j++) {
                ull bh = sB2h[(kk * 8 + j) * 32 + lane];
                ull bl = sB2l[(kk * 8 + j) * 32 + lane];
                uint32_t bh0 = (uint32_t)bh, bh1 = (uint32_t)(bh >> 32);
                uint32_t bl0 = (uint32_t)bl, bl1 = (uint32_t)(bl >> 32);
                mma16(D2[j], a2h, bh0, bh1);
                mma16(D2[j], a2l, bh0, bh1);
                mma16(D2[j], a2h, bl0, bl1);
            }
        }
        float hj2[8][4];
#pragma unroll
        for (int j = 0; j < 8; j++) {
            hj2[j][0] = swishf(D2[j][0]);
            hj2[j][1] = swishf(D2[j][1]);
            hj2[j][2] = swishf(D2[j][2]);
            hj2[j][3] = swishf(D2[j][3]);
        }

        // ===== phase 3 (bf16 k16): mix = h2 @ W3s (N=8) =====
        float D3a[4] = {0.f, 0.f, 0.f, 0.f};
        float D3b[4] = {0.f, 0.f, 0.f, 0.f};
#pragma unroll
        for (int kk = 0; kk < 4; kk++) {
            uint32_t a3h[4], a3l[4];
            bfsplit2(hj2[2 * kk][0],     hj2[2 * kk][1],     a3h[0], a3l[0]);
            bfsplit2(hj2[2 * kk][2],     hj2[2 * kk][3],     a3h[1], a3l[1]);
            bfsplit2(hj2[2 * kk + 1][0], hj2[2 * kk + 1][1], a3h[2], a3l[2]);
            bfsplit2(hj2[2 * kk + 1][2], hj2[2 * kk + 1][3], a3h[3], a3l[3]);
            ull bh = sB3h[kk * 32 + lane];
            ull bl = sB3l[kk * 32 + lane];
            uint32_t bh0 = (uint32_t)bh, bh1 = (uint32_t)(bh >> 32);
            uint32_t bl0 = (uint32_t)bl, bl1 = (uint32_t)(bl >> 32);
            float* Dc = (kk & 1) ? D3b : D3a;
            mma16(Dc, a3h, bh0, bh1);
            mma16(Dc, a3l, bh0, bh1);
            mma16(Dc, a3h, bl0, bl1);
        }
        float o0 = D3a[0] + D3b[0];
        float o1 = D3a[1] + D3b[1];
        float o2 = D3a[2] + D3b[2];
        float o3 = D3a[3] + D3b[3];

        int e0 = base + g, e1 = base + g + 8;
        if (e0 < ne) *(float2*)&g_mix[e0 * 8 + 2 * t4] = make_float2(o0, o1);
        if (e1 < ne) *(float2*)&g_mix[e1 * 8 + 2 * t4] = make_float2(o2, o3);
    }
}

// ---------------------------------------------------------------------------
// node pre: su/vu (packed record) from current s/v, zero agg (12 floats)
// ---------------------------------------------------------------------------
__global__ void k_node_pre(const float* __restrict__ Wus,
                           const float* __restrict__ Wuv, int nn) {
    int n = blockIdx.x * blockDim.x + threadIdx.x;
    if (n >= nn) return;
    float s = g_s[n];
    float su = s * Wus[0];
    float w00 = Wuv[0], w01 = Wuv[1], w10 = Wuv[2], w11 = Wuv[3];
    float vu0[3], vu1[3];
#pragma unroll
    for (int c = 0; c < 3; c++) {
        float a = g_v[n * 6 + c], b = g_v[n * 6 + 3 + c];
        vu0[c] = (a * w00 + b * w10) * INV_SQRT2;
        vu1[c] = (a * w01 + b * w11) * INV_SQRT2;
    }
    *(float4*)&g_vus[n * 8]     = make_float4(vu0[0], vu0[1], vu0[2], su);
    *(float4*)&g_vus[n * 8 + 4] = make_float4(vu1[0], vu1[1], vu1[2], 0.0f);
    float4 z = make_float4(0.f, 0.f, 0.f, 0.f);
#pragma unroll
    for (int i = 0; i < 3; i++) *(float4*)&g_agg[n * 12 + 4 * i] = z;
}

// ---------------------------------------------------------------------------
// per-edge message, PRE-CONTRACTED through Wds/Wdv -> 9 atomic lanes
// agg layout: [0..2]=sd, [3..5]=vd(k=0), [6..8]=vd(k=1)
// ---------------------------------------------------------------------------
__global__ void k_edge(const int* __restrict__ snd,
                       const int* __restrict__ rcv,
                       const float* __restrict__ Wds,
                       const float* __restrict__ Wdv, int ne) {
    int e = blockIdx.x * blockDim.x + threadIdx.x;
    if (e >= ne) return;
    int s = snd[e], r = rcv[e];
    float4 nh = *(const float4*)&g_nhat[e * 4];
    float nx = nh.x, ny = nh.y, nz = nh.z;
    float4 m0 = *(const float4*)&g_mix[e * 8];
    float4 m1 = *(const float4*)&g_mix[e * 8 + 4];

    float4 p0 = *(const float4*)&g_vus[s * 8];
    float4 p1 = *(const float4*)&g_vus[s * 8 + 4];
    float se = p0.w;
    float v0x = p0.x, v0y = p0.y, v0z = p0.z;
    float v1x = p1.x, v1y = p1.y, v1z = p1.z;

    float d0 = v0x * nx + v0y * ny + v0z * nz;
    float d1 = v1x * nx + v1y * ny + v1z * nz;

    const float third = 1.0f / 3.0f;
    float c0 = C121_F * m1.y;
    float c1 = C121_F * m1.z;
    float cb = SQRT3_F * se * m1.w;

    // scalar messages -> contracted through Wds
    float ms0 = se * m0.x;
    float ms1 = d0 * m0.y;
    float ms2 = d1 * m0.z;
    float sd[3];
#pragma unroll
    for (int k = 0; k < 3; k++)
        sd[k] = (ms0 * Wds[k] + ms1 * Wds[3 + k] + ms2 * Wds[6 + k]) * INV_SQRT3;

    // vector message rows -> contracted through Wdv
    float vd[2][3];
#pragma unroll
    for (int c = 0; c < 3; c++) {
        float n_c = (c == 0) ? nx : ((c == 1) ? ny : nz);
        float v0c = (c == 0) ? v0x : ((c == 1) ? v0y : v0z);
        float v1c = (c == 0) ? v1x : ((c == 1) ? v1y : v1z);
        float r0 = v0c * m0.w;
        float r1 = v1c * m1.x;
        float r2 = c0 * (d0 * n_c - v0c * third);
        float r3 = c1 * (d1 * n_c - v1c * third);
        float r4 = cb * n_c;
#pragma unroll
        for (int k = 0; k < 2; k++) {
            float acc = r0 * Wdv[k];
            acc = fmaf(r1, Wdv[2 + k], acc);
            acc = fmaf(r2, Wdv[4 + k], acc);
            acc = fmaf(r3, Wdv[6 + k], acc);
            acc = fmaf(r4, Wdv[8 + k], acc);
            vd[k][c] = acc * INV_SQRT5;
        }
    }

    float* base = &g_agg[r * 12];
    asm volatile("red.global.add.v4.f32 [%0], {%1, %2, %3, %4};"
                 :: "l"(base), "f"(sd[0]), "f"(sd[1]), "f"(sd[2]), "f"(vd[0][0])
                 : "memory");
    asm volatile("red.global.add.v4.f32 [%0], {%1, %2, %3, %4};"
                 :: "l"(base + 4), "f"(vd[0][1]), "f"(vd[0][2]),
                    "f"(vd[1][0]), "f"(vd[1][1])
                 : "memory");
    asm volatile("red.global.add.f32 [%0], %1;"
                 :: "l"(base + 8), "f"(vd[1][2]) : "memory");
}

// ---------------------------------------------------------------------------
// node post: residual, gates, update s/v (agg already contracted)
// ---------------------------------------------------------------------------
__global__ void k_node_post(const float* __restrict__ Wss,
                            const float* __restrict__ Wsv,
                            float* __restrict__ out, int write_out, int nn) {
    int n = blockIdx.x * blockDim.x + threadIdx.x;
    if (n >= nn) return;
    float s = g_s[n];
    float v[6];
#pragma unroll
    for (int i = 0; i < 6; i++) v[i] = g_v[n * 6 + i];
    float agg[9];
#pragma unroll
    for (int i = 0; i < 9; i++) agg[i] = g_agg[n * 12 + i];

    float st[3];
#pragma unroll
    for (int k = 0; k < 3; k++) st[k] = agg[k] + s * Wss[k];

    float vt[6];
#pragma unroll
    for (int k = 0; k < 2; k++) {
#pragma unroll
        for (int c = 0; c < 3; c++) {
            float vsc = (v[c] * Wsv[0 * 2 + k] + v[3 + c] * Wsv[1 * 2 + k]) * INV_SQRT2;
            vt[k * 3 + c] = agg[3 + 3 * k + c] + vsc;
        }
    }
    float ns = swish_exact(st[0]);
    float g1 = swish_exact(st[1]);
    float g2 = swish_exact(st[2]);
    g_s[n] = ns;
#pragma unroll
    for (int c = 0; c < 3; c++) {
        float nv0 = vt[c] * g1;
        float nv1 = vt[3 + c] * g2;
        g_v[n * 6 + c]     = nv0;
        g_v[n * 6 + 3 + c] = nv1;
        if (write_out) out[n * 3 + c] = nv0;
    }
}

// ---------------------------------------------------------------------------
// launch
// ---------------------------------------------------------------------------
extern "C" void kernel_launch(void* const* d_in, const int* in_sizes, int n_in,
                              void* d_out, int out_size) {
    const float* pos = (const float*)d_in[0];
    const float* nf  = (const float*)d_in[1];
    const int* snd   = (const int*)d_in[2];
    const int* rcv   = (const int*)d_in[3];
    const float* Wss = (const float*)d_in[4];
    const float* Wsv = (const float*)d_in[5];
    const float* Wus = (const float*)d_in[6];
    const float* Wuv = (const float*)d_in[7];
    const float* W1  = (const float*)d_in[8];
    const float* W2  = (const float*)d_in[9];
    const float* W3  = (const float*)d_in[10];
    const float* Wds = (const float*)d_in[11];
    const float* Wdv = (const float*)d_in[12];
    float* out = (float*)d_out;

    int ne = in_sizes[2];
    int nn = in_sizes[0] / 3;

    int nb_n = (nn + 255) / 256;
    int nb_e = (ne + 255) / 256;
    int ntiles = (ne + 63) / 64;
    int nb_t = ntiles < 888 ? ntiles : 888;

    k_init<<<nb_n, 256>>>(nf, nn);
    k_geom<<<nb_e, 256>>>(pos, snd, rcv, ne);

    for (int l = 0; l < 3; l++) {
        k_node_pre<<<nb_n, 256>>>(Wus + l * 1, Wuv + l * 4, nn);
        k_mix_mma<<<nb_t, 128>>>(W1 + l * 512, W2 + l * 4096, W3 + l * 512, ne, ntiles);
        k_edge<<<nb_e, 256>>>(snd, rcv, Wds + l * 9, Wdv + l * 10, ne);
        k_node_post<<<nb_n, 256>>>(Wss + l * 3, Wsv + l * 4,
                                   out, (l == 2) ? 1 : 0, nn);
    }
}

// round 14
// speedup vs baseline: 1.5406x; 1.5406x over previous
#include <cuda_runtime.h>
#include <cuda_bf16.h>
#include <math.h>
#include <stdint.h>

typedef unsigned long long ull;

#define NN_MAX 50000
#define NE_MAX 1000000

// ---- device-global scratch (no allocations allowed) ----
__device__ float g_s[NN_MAX];
__device__ float g_v[NN_MAX * 6];
__device__ float g_vus[NN_MAX * 8];
__device__ float g_agg[NN_MAX * 12];     // pre-contracted: sd[3] + vd[6], pad 12
__device__ float g_nhat[NE_MAX * 4];
__device__ float g_radial[NE_MAX * 8];
__device__ float g_mix[NE_MAX * 8];

#define INV_SQRT2 0.70710678118654752f
#define INV_SQRT3 0.57735026918962576f
#define INV_SQRT5 0.44721359549995794f
#define INV_SQRT8 0.35355339059327376f
#define SQRT2_F   1.4142135623730951f
#define C121_F    2.1213203435596424f
#define SQRT3_F   1.7320508075688772f

// swish via HW tanh: swish(x) = 0.5x + 0.5x*tanh(0.5x)
__device__ __forceinline__ float swishf(float x) {
    float hx = 0.5f * x;
    float t;
    asm("tanh.approx.f32 %0, %1;" : "=f"(t) : "f"(hx));
    return fmaf(hx, t, hx);
}
__device__ __forceinline__ float swish_exact(float x) {
    return __fdividef(x, 1.0f + __expf(-x));
}

// ---- tf32 split (phase 1) ----
__device__ __forceinline__ void tf32split(float x, uint32_t& hi, uint32_t& lo) {
    asm("cvt.rna.tf32.f32 %0, %1;" : "=r"(hi) : "f"(x));
    lo = __float_as_uint(x - __uint_as_float(hi));
}

// ---- bf16 2-way split, packed pair (x -> low half, y -> high half) ----
__device__ __forceinline__ void bfsplit2(float x, float y,
                                         uint32_t& hp, uint32_t& lp) {
    uint32_t h;
    asm("cvt.rn.bf16x2.f32 %0, %1, %2;" : "=r"(h) : "f"(y), "f"(x));
    float xh = __uint_as_float(h << 16);
    float yh = __uint_as_float(h & 0xFFFF0000u);
    float xr = x - xh;
    float yr = y - yh;
    uint32_t l;
    asm("cvt.rn.bf16x2.f32 %0, %1, %2;" : "=r"(l) : "f"(yr), "f"(xr));
    hp = h;
    lp = l;
}

// ---- warp MMAs ----
__device__ __forceinline__ void mma8(float d[4], const uint32_t a[4],
                                     uint32_t b0, uint32_t b1) {
    asm volatile(
        "mma.sync.aligned.m16n8k8.row.col.f32.tf32.tf32.f32 "
        "{%0,%1,%2,%3}, {%4,%5,%6,%7}, {%8,%9}, {%0,%1,%2,%3};"
        : "+f"(d[0]), "+f"(d[1]), "+f"(d[2]), "+f"(d[3])
        : "r"(a[0]), "r"(a[1]), "r"(a[2]), "r"(a[3]), "r"(b0), "r"(b1));
}
__device__ __forceinline__ void mma16(float d[4], const uint32_t a[4],
                                      uint32_t b0, uint32_t b1) {
    asm volatile(
        "mma.sync.aligned.m16n8k16.row.col.f32.bf16.bf16.f32 "
        "{%0,%1,%2,%3}, {%4,%5,%6,%7}, {%8,%9}, {%0,%1,%2,%3};"
        : "+f"(d[0]), "+f"(d[1]), "+f"(d[2]), "+f"(d[3])
        : "r"(a[0]), "r"(a[1]), "r"(a[2]), "r"(a[3]), "r"(b0), "r"(b1));
}

// ---------------------------------------------------------------------------
// init node state
// ---------------------------------------------------------------------------
__global__ void k_init(const float* __restrict__ nf, int nn) {
    int n = blockIdx.x * blockDim.x + threadIdx.x;
    if (n >= nn) return;
    g_s[n] = nf[n * 7];
#pragma unroll
    for (int i = 0; i < 6; i++) g_v[n * 6 + i] = nf[n * 7 + 1 + i];
}

// ---------------------------------------------------------------------------
// per-edge geometry
// ---------------------------------------------------------------------------
__global__ void k_geom(const float* __restrict__ pos,
                       const int* __restrict__ snd,
                       const int* __restrict__ rcv, int ne) {
    int e = blockIdx.x * blockDim.x + threadIdx.x;
    if (e >= ne) return;
    int s = snd[e], r = rcv[e];
    float vx = pos[r * 3 + 0] - pos[s * 3 + 0];
    float vy = pos[r * 3 + 1] - pos[s * 3 + 1];
    float vz = pos[r * 3 + 2] - pos[s * 3 + 2];
    float len = sqrtf(vx * vx + vy * vy + vz * vz);
    float inv = (len == 0.0f) ? 1.0f : (1.0f / len);
    *(float4*)&g_nhat[e * 4] = make_float4(vx * inv, vy * inv, vz * inv, 0.0f);

    float env = 0.0f;
    if (len < 1.0f) {
        float x = len;
        float x2 = x * x, x3 = x2 * x;
        float x6 = x3 * x3, x7 = x6 * x, x8 = x7 * x;
        env = 1.0f - 28.0f * x6 + 48.0f * x7 - 21.0f * x8;
    }
    float coef = (len == 0.0f) ? 0.0f : (SQRT2_F * env * inv);

    float s1, c1;
    sincospif(len, &s1, &c1);
    float out[8];
    float sm1 = 0.0f, sk = s1;
#pragma unroll
    for (int k = 0; k < 8; k++) {
        out[k] = sk * coef;
        float nx = 2.0f * c1 * sk - sm1;
        sm1 = sk; sk = nx;
    }
    *(float4*)&g_radial[e * 8]     = make_float4(out[0], out[1], out[2], out[3]);
    *(float4*)&g_radial[e * 8 + 4] = make_float4(out[4], out[5], out[6], out[7]);
}

// ---------------------------------------------------------------------------
// radial MLP (EXACT R12 version): phase1 tf32 m16n8k8 (3-term),
// phases 2-3 bf16 m16n8k16 (2-way split, 3 terms). No shuffles.
// ---------------------------------------------------------------------------
__global__ __launch_bounds__(128)
void k_mix_mma(const float* __restrict__ W1, const float* __restrict__ W2,
               const float* __restrict__ W3, int ne, int ntiles) {
    __shared__ ull sB1h[8 * 32],  sB1l[8 * 32];    // W1 tf32 packs
    __shared__ ull sB2h[32 * 32], sB2l[32 * 32];   // W2 bf16 packs
    __shared__ ull sB3h[4 * 32],  sB3l[4 * 32];    // W3 bf16 packs

    int tid = threadIdx.x;

    for (int idx = tid; idx < 256; idx += 128) {
        int j = idx >> 5, l = idx & 31;
        float w0 = W1[(l & 3) * 64 + 8 * j + (l >> 2)] * INV_SQRT8;
        float w1 = W1[((l & 3) + 4) * 64 + 8 * j + (l >> 2)] * INV_SQRT8;
        uint32_t h0, l0, h1, l1;
        tf32split(w0, h0, l0); tf32split(w1, h1, l1);
        sB1h[idx] = ((ull)h1 << 32) | h0;
        sB1l[idx] = ((ull)l1 << 32) | l0;
    }
    for (int idx = tid; idx < 1024; idx += 128) {
        int t = idx >> 5, l = idx & 31;
        int kk = t >> 3, j = t & 7;
        int g = l >> 2, t4 = l & 3;
        int col = 8 * j + g;
        int r0 = 16 * kk + 2 * t4;
        float w00 = W2[(r0 + 0) * 64 + col] * 0.125f;
        float w01 = W2[(r0 + 1) * 64 + col] * 0.125f;
        float w10 = W2[(r0 + 8) * 64 + col] * 0.125f;
        float w11 = W2[(r0 + 9) * 64 + col] * 0.125f;
        uint32_t b0h, b0l, b1h, b1l;
        bfsplit2(w00, w01, b0h, b0l);
        bfsplit2(w10, w11, b1h, b1l);
        sB2h[idx] = ((ull)b1h << 32) | b0h;
        sB2l[idx] = ((ull)b1l << 32) | b0l;
    }
    for (int idx = tid; idx < 128; idx += 128) {
        int kk = idx >> 5, l = idx & 31;
        int g = l >> 2, t4 = l & 3;
        int r0 = 16 * kk + 2 * t4;
        float w00 = W3[(r0 + 0) * 8 + g] * 0.125f;
        float w01 = W3[(r0 + 1) * 8 + g] * 0.125f;
        float w10 = W3[(r0 + 8) * 8 + g] * 0.125f;
        float w11 = W3[(r0 + 9) * 8 + g] * 0.125f;
        uint32_t b0h, b0l, b1h, b1l;
        bfsplit2(w00, w01, b0h, b0l);
        bfsplit2(w10, w11, b1h, b1l);
        sB3h[idx] = ((ull)b1h << 32) | b0h;
        sB3l[idx] = ((ull)b1l << 32) | b0l;
    }
    __syncthreads();

    int w    = tid >> 5;
    int lane = tid & 31;
    int g    = lane >> 2;
    int t4   = lane & 3;

    for (int tile = blockIdx.x; tile < ntiles; tile += gridDim.x) {
        int base = tile * 64 + w * 16;
        int eg  = base + g;      if (eg  >= ne) eg  = ne - 1;
        int eg8 = base + g + 8;  if (eg8 >= ne) eg8 = ne - 1;

        // ===== phase 1 (tf32): h1 = swish(radial @ W1s) =====
        uint32_t ah[4], al[4];
        {
            float r0 = g_radial[eg  * 8 + t4];
            float r1 = g_radial[eg8 * 8 + t4];
            float r2 = g_radial[eg  * 8 + t4 + 4];
            float r3 = g_radial[eg8 * 8 + t4 + 4];
            tf32split(r0, ah[0], al[0]);
            tf32split(r1, ah[1], al[1]);
            tf32split(r2, ah[2], al[2]);
            tf32split(r3, ah[3], al[3]);
        }
        float hj[8][4];
#pragma unroll
        for (int j = 0; j < 8; j++) {
            float D[4] = {0.f, 0.f, 0.f, 0.f};
            ull bh = sB1h[j * 32 + lane];
            ull bl = sB1l[j * 32 + lane];
            uint32_t bh0 = (uint32_t)bh, bh1 = (uint32_t)(bh >> 32);
            uint32_t bl0 = (uint32_t)bl, bl1 = (uint32_t)(bl >> 32);
            mma8(D, ah, bh0, bh1);
            mma8(D, al, bh0, bh1);
            mma8(D, ah, bl0, bl1);
            hj[j][0] = swishf(D[0]);
            hj[j][1] = swishf(D[1]);
            hj[j][2] = swishf(D[2]);
            hj[j][3] = swishf(D[3]);
        }

        // ===== phase 2 (bf16 k16): h2 = swish(h1 @ W2s) =====
        float D2[8][4];
#pragma unroll
        for (int j = 0; j < 8; j++)
#pragma unroll
            for (int q = 0; q < 4; q++) D2[j][q] = 0.f;

#pragma unroll
        for (int kk = 0; kk < 4; kk++) {
            uint32_t a2h[4], a2l[4];
            bfsplit2(hj[2 * kk][0],     hj[2 * kk][1],     a2h[0], a2l[0]);
            bfsplit2(hj[2 * kk][2],     hj[2 * kk][3],     a2h[1], a2l[1]);
            bfsplit2(hj[2 * kk + 1][0], hj[2 * kk + 1][1], a2h[2], a2l[2]);
            bfsplit2(hj[2 * kk + 1][2], hj[2 * kk + 1][3], a2h[3], a2l[3]);
#pragma unroll
            for (int j = 0; j < 8; j++) {
                ull bh = sB2h[(kk * 8 + j) * 32 + lane];
                ull bl = sB2l[(kk * 8 + j) * 32 + lane];
                uint32_t bh0 = (uint32_t)bh, bh1 = (uint32_t)(bh >> 32);
                uint32_t bl0 = (uint32_t)bl, bl1 = (uint32_t)(bl >> 32);
                mma16(D2[j], a2h, bh0, bh1);
                mma16(D2[j], a2l, bh0, bh1);
                mma16(D2[j], a2h, bl0, bl1);
            }
        }
        float hj2[8][4];
#pragma unroll
        for (int j = 0; j < 8; j++) {
            hj2[j][0] = swishf(D2[j][0]);
            hj2[j][1] = swishf(D2[j][1]);
            hj2[j][2] = swishf(D2[j][2]);
            hj2[j][3] = swishf(D2[j][3]);
        }

        // ===== phase 3 (bf16 k16): mix = h2 @ W3s (N=8) =====
        float D3a[4] = {0.f, 0.f, 0.f, 0.f};
        float D3b[4] = {0.f, 0.f, 0.f, 0.f};
#pragma unroll
        for (int kk = 0; kk < 4; kk++) {
            uint32_t a3h[4], a3l[4];
            bfsplit2(hj2[2 * kk][0],     hj2[2 * kk][1],     a3h[0], a3l[0]);
            bfsplit2(hj2[2 * kk][2],     hj2[2 * kk][3],     a3h[1], a3l[1]);
            bfsplit2(hj2[2 * kk + 1][0], hj2[2 * kk + 1][1], a3h[2], a3l[2]);
            bfsplit2(hj2[2 * kk + 1][2], hj2[2 * kk + 1][3], a3h[3], a3l[3]);
            ull bh = sB3h[kk * 32 + lane];
            ull bl = sB3l[kk * 32 + lane];
            uint32_t bh0 = (uint32_t)bh, bh1 = (uint32_t)(bh >> 32);
            uint32_t bl0 = (uint32_t)bl, bl1 = (uint32_t)(bl >> 32);
            float* Dc = (kk & 1) ? D3b : D3a;
            mma16(Dc, a3h, bh0, bh1);
            mma16(Dc, a3l, bh0, bh1);
            mma16(Dc, a3h, bl0, bl1);
        }
        float o0 = D3a[0] + D3b[0];
        float o1 = D3a[1] + D3b[1];
        float o2 = D3a[2] + D3b[2];
        float o3 = D3a[3] + D3b[3];

        int e0 = base + g, e1 = base + g + 8;
        if (e0 < ne) *(float2*)&g_mix[e0 * 8 + 2 * t4] = make_float2(o0, o1);
        if (e1 < ne) *(float2*)&g_mix[e1 * 8 + 2 * t4] = make_float2(o2, o3);
    }
}

// ---------------------------------------------------------------------------
// node pre: su/vu (packed record) from current s/v, zero agg (12 floats)
// ---------------------------------------------------------------------------
__global__ void k_node_pre(const float* __restrict__ Wus,
                           const float* __restrict__ Wuv, int nn) {
    int n = blockIdx.x * blockDim.x + threadIdx.x;
    if (n >= nn) return;
    float s = g_s[n];
    float su = s * Wus[0];
    float w00 = Wuv[0], w01 = Wuv[1], w10 = Wuv[2], w11 = Wuv[3];
    float vu0[3], vu1[3];
#pragma unroll
    for (int c = 0; c < 3; c++) {
        float a = g_v[n * 6 + c], b = g_v[n * 6 + 3 + c];
        vu0[c] = (a * w00 + b * w10) * INV_SQRT2;
        vu1[c] = (a * w01 + b * w11) * INV_SQRT2;
    }
    *(float4*)&g_vus[n * 8]     = make_float4(vu0[0], vu0[1], vu0[2], su);
    *(float4*)&g_vus[n * 8 + 4] = make_float4(vu1[0], vu1[1], vu1[2], 0.0f);
    float4 z = make_float4(0.f, 0.f, 0.f, 0.f);
#pragma unroll
    for (int i = 0; i < 3; i++) *(float4*)&g_agg[n * 12 + 4 * i] = z;
}

// ---------------------------------------------------------------------------
// per-edge message, PRE-CONTRACTED through Wds/Wdv -> 9 atomic lanes
// agg layout: [0..2]=sd, [3..5]=vd(k=0), [6..8]=vd(k=1)
// ---------------------------------------------------------------------------
__global__ void k_edge(const int* __restrict__ snd,
                       const int* __restrict__ rcv,
                       const float* __restrict__ Wds,
                       const float* __restrict__ Wdv, int ne) {
    int e = blockIdx.x * blockDim.x + threadIdx.x;
    if (e >= ne) return;
    int s = snd[e], r = rcv[e];
    float4 nh = *(const float4*)&g_nhat[e * 4];
    float nx = nh.x, ny = nh.y, nz = nh.z;
    float4 m0 = *(const float4*)&g_mix[e * 8];
    float4 m1 = *(const float4*)&g_mix[e * 8 + 4];

    float4 p0 = *(const float4*)&g_vus[s * 8];
    float4 p1 = *(const float4*)&g_vus[s * 8 + 4];
    float se = p0.w;
    float v0x = p0.x, v0y = p0.y, v0z = p0.z;
    float v1x = p1.x, v1y = p1.y, v1z = p1.z;

    float d0 = v0x * nx + v0y * ny + v0z * nz;
    float d1 = v1x * nx + v1y * ny + v1z * nz;

    const float third = 1.0f / 3.0f;
    float c0 = C121_F * m1.y;
    float c1 = C121_F * m1.z;
    float cb = SQRT3_F * se * m1.w;

    // scalar messages -> contracted through Wds
    float ms0 = se * m0.x;
    float ms1 = d0 * m0.y;
    float ms2 = d1 * m0.z;
    float sd[3];
#pragma unroll
    for (int k = 0; k < 3; k++)
        sd[k] = (ms0 * Wds[k] + ms1 * Wds[3 + k] + ms2 * Wds[6 + k]) * INV_SQRT3;

    // vector message rows -> contracted through Wdv
    float vd[2][3];
#pragma unroll
    for (int c = 0; c < 3; c++) {
        float n_c = (c == 0) ? nx : ((c == 1) ? ny : nz);
        float v0c = (c == 0) ? v0x : ((c == 1) ? v0y : v0z);
        float v1c = (c == 0) ? v1x : ((c == 1) ? v1y : v1z);
        float r0 = v0c * m0.w;
        float r1 = v1c * m1.x;
        float r2 = c0 * (d0 * n_c - v0c * third);
        float r3 = c1 * (d1 * n_c - v1c * third);
        float r4 = cb * n_c;
#pragma unroll
        for (int k = 0; k < 2; k++) {
            float acc = r0 * Wdv[k];
            acc = fmaf(r1, Wdv[2 + k], acc);
            acc = fmaf(r2, Wdv[4 + k], acc);
            acc = fmaf(r3, Wdv[6 + k], acc);
            acc = fmaf(r4, Wdv[8 + k], acc);
            vd[k][c] = acc * INV_SQRT5;
        }
    }

    float* base = &g_agg[r * 12];
    asm volatile("red.global.add.v4.f32 [%0], {%1, %2, %3, %4};"
                 :: "l"(base), "f"(sd[0]), "f"(sd[1]), "f"(sd[2]), "f"(vd[0][0])
                 : "memory");
    asm volatile("red.global.add.v4.f32 [%0], {%1, %2, %3, %4};"
                 :: "l"(base + 4), "f"(vd[0][1]), "f"(vd[0][2]),
                    "f"(vd[1][0]), "f"(vd[1][1])
                 : "memory");
    asm volatile("red.global.add.f32 [%0], %1;"
                 :: "l"(base + 8), "f"(vd[1][2]) : "memory");
}

// ---------------------------------------------------------------------------
// node post: residual, gates, update s/v (agg already contracted)
// ---------------------------------------------------------------------------
__global__ void k_node_post(const float* __restrict__ Wss,
                            const float* __restrict__ Wsv,
                            float* __restrict__ out, int write_out, int nn) {
    int n = blockIdx.x * blockDim.x + threadIdx.x;
    if (n >= nn) return;
    float s = g_s[n];
    float v[6];
#pragma unroll
    for (int i = 0; i < 6; i++) v[i] = g_v[n * 6 + i];
    float agg[9];
#pragma unroll
    for (int i = 0; i < 9; i++) agg[i] = g_agg[n * 12 + i];

    float st[3];
#pragma unroll
    for (int k = 0; k < 3; k++) st[k] = agg[k] + s * Wss[k];

    float vt[6];
#pragma unroll
    for (int k = 0; k < 2; k++) {
#pragma unroll
        for (int c = 0; c < 3; c++) {
            float vsc = (v[c] * Wsv[0 * 2 + k] + v[3 + c] * Wsv[1 * 2 + k]) * INV_SQRT2;
            vt[k * 3 + c] = agg[3 + 3 * k + c] + vsc;
        }
    }
    float ns = swish_exact(st[0]);
    float g1 = swish_exact(st[1]);
    float g2 = swish_exact(st[2]);
    g_s[n] = ns;
#pragma unroll
    for (int c = 0; c < 3; c++) {
        float nv0 = vt[c] * g1;
        float nv1 = vt[3 + c] * g2;
        g_v[n * 6 + c]     = nv0;
        g_v[n * 6 + 3 + c] = nv1;
        if (write_out) out[n * 3 + c] = nv0;
    }
}

// ---------------------------------------------------------------------------
// launch
// ---------------------------------------------------------------------------
extern "C" void kernel_launch(void* const* d_in, const int* in_sizes, int n_in,
                              void* d_out, int out_size) {
    const float* pos = (const float*)d_in[0];
    const float* nf  = (const float*)d_in[1];
    const int* snd   = (const int*)d_in[2];
    const int* rcv   = (const int*)d_in[3];
    const float* Wss = (const float*)d_in[4];
    const float* Wsv = (const float*)d_in[5];
    const float* Wus = (const float*)d_in[6];
    const float* Wuv = (const float*)d_in[7];
    const float* W1  = (const float*)d_in[8];
    const float* W2  = (const float*)d_in[9];
    const float* W3  = (const float*)d_in[10];
    const float* Wds = (const float*)d_in[11];
    const float* Wdv = (const float*)d_in[12];
    float* out = (float*)d_out;

    int ne = in_sizes[2];
    int nn = in_sizes[0] / 3;

    int nb_n = (nn + 255) / 256;
    int nb_e = (ne + 255) / 256;
    int ntiles = (ne + 63) / 64;
    int nb_t = ntiles < 888 ? ntiles : 888;

    k_init<<<nb_n, 256>>>(nf, nn);
    k_geom<<<nb_e, 256>>>(pos, snd, rcv, ne);

    for (int l = 0; l < 3; l++) {
        k_node_pre<<<nb_n, 256>>>(Wus + l * 1, Wuv + l * 4, nn);
        k_mix_mma<<<nb_t, 128>>>(W1 + l * 512, W2 + l * 4096, W3 + l * 512, ne, ntiles);
        k_edge<<<nb_e, 256>>>(snd, rcv, Wds + l * 9, Wdv + l * 10, ne);
        k_node_post<<<nb_n, 256>>>(Wss + l * 3, Wsv + l * 4,
                                   out, (l == 2) ? 1 : 0, nn);
    }
}

// round 16
// speedup vs baseline: 1.6996x; 1.1032x over previous
#include <cuda_runtime.h>
#include <cuda_bf16.h>
#include <math.h>
#include <stdint.h>

typedef unsigned long long ull;

#define NN_MAX 50000
#define NE_MAX 1000000

// ---- device-global scratch (no allocations allowed) ----
__device__ float g_s[NN_MAX];
__device__ float g_v[NN_MAX * 6];
__device__ float g_vus[NN_MAX * 8];
__device__ float g_agg[NN_MAX * 12];     // pre-contracted: sd[3] + vd[6], pad 12
__device__ float g_nhat[NE_MAX * 4];
__device__ float g_radial[NE_MAX * 8];

#define INV_SQRT2 0.70710678118654752f
#define INV_SQRT3 0.57735026918962576f
#define INV_SQRT5 0.44721359549995794f
#define INV_SQRT8 0.35355339059327376f
#define SQRT2_F   1.4142135623730951f
#define C121_F    2.1213203435596424f
#define SQRT3_F   1.7320508075688772f

// swish via HW tanh: swish(x) = 0.5x + 0.5x*tanh(0.5x)
__device__ __forceinline__ float swishf(float x) {
    float hx = 0.5f * x;
    float t;
    asm("tanh.approx.f32 %0, %1;" : "=f"(t) : "f"(hx));
    return fmaf(hx, t, hx);
}
__device__ __forceinline__ float swish_exact(float x) {
    return __fdividef(x, 1.0f + __expf(-x));
}

// ---- tf32 split (phase 1) ----
__device__ __forceinline__ void tf32split(float x, uint32_t& hi, uint32_t& lo) {
    asm("cvt.rna.tf32.f32 %0, %1;" : "=r"(hi) : "f"(x));
    lo = __float_as_uint(x - __uint_as_float(hi));
}

// ---- bf16 2-way split, packed pair (x -> low half, y -> high half) ----
__device__ __forceinline__ void bfsplit2(float x, float y,
                                         uint32_t& hp, uint32_t& lp) {
    uint32_t h;
    asm("cvt.rn.bf16x2.f32 %0, %1, %2;" : "=r"(h) : "f"(y), "f"(x));
    float xh = __uint_as_float(h << 16);
    float yh = __uint_as_float(h & 0xFFFF0000u);
    float xr = x - xh;
    float yr = y - yh;
    uint32_t l;
    asm("cvt.rn.bf16x2.f32 %0, %1, %2;" : "=r"(l) : "f"(yr), "f"(xr));
    hp = h;
    lp = l;
}

// ---- warp MMAs ----
__device__ __forceinline__ void mma8(float d[4], const uint32_t a[4],
                                     uint32_t b0, uint32_t b1) {
    asm volatile(
        "mma.sync.aligned.m16n8k8.row.col.f32.tf32.tf32.f32 "
        "{%0,%1,%2,%3}, {%4,%5,%6,%7}, {%8,%9}, {%0,%1,%2,%3};"
        : "+f"(d[0]), "+f"(d[1]), "+f"(d[2]), "+f"(d[3])
        : "r"(a[0]), "r"(a[1]), "r"(a[2]), "r"(a[3]), "r"(b0), "r"(b1));
}
__device__ __forceinline__ void mma16(float d[4], const uint32_t a[4],
                                      uint32_t b0, uint32_t b1) {
    asm volatile(
        "mma.sync.aligned.m16n8k16.row.col.f32.bf16.bf16.f32 "
        "{%0,%1,%2,%3}, {%4,%5,%6,%7}, {%8,%9}, {%0,%1,%2,%3};"
        : "+f"(d[0]), "+f"(d[1]), "+f"(d[2]), "+f"(d[3])
        : "r"(a[0]), "r"(a[1]), "r"(a[2]), "r"(a[3]), "r"(b0), "r"(b1));
}

// ---------------------------------------------------------------------------
// init node state
// ---------------------------------------------------------------------------
__global__ void k_init(const float* __restrict__ nf, int nn) {
    int n = blockIdx.x * blockDim.x + threadIdx.x;
    if (n >= nn) return;
    g_s[n] = nf[n * 7];
#pragma unroll
    for (int i = 0; i < 6; i++) g_v[n * 6 + i] = nf[n * 7 + 1 + i];
}

// ---------------------------------------------------------------------------
// per-edge geometry
// ---------------------------------------------------------------------------
__global__ void k_geom(const float* __restrict__ pos,
                       const int* __restrict__ snd,
                       const int* __restrict__ rcv, int ne) {
    int e = blockIdx.x * blockDim.x + threadIdx.x;
    if (e >= ne) return;
    int s = snd[e], r = rcv[e];
    float vx = pos[r * 3 + 0] - pos[s * 3 + 0];
    float vy = pos[r * 3 + 1] - pos[s * 3 + 1];
    float vz = pos[r * 3 + 2] - pos[s * 3 + 2];
    float len = sqrtf(vx * vx + vy * vy + vz * vz);
    float inv = (len == 0.0f) ? 1.0f : (1.0f / len);
    *(float4*)&g_nhat[e * 4] = make_float4(vx * inv, vy * inv, vz * inv, 0.0f);

    float env = 0.0f;
    if (len < 1.0f) {
        float x = len;
        float x2 = x * x, x3 = x2 * x;
        float x6 = x3 * x3, x7 = x6 * x, x8 = x7 * x;
        env = 1.0f - 28.0f * x6 + 48.0f * x7 - 21.0f * x8;
    }
    float coef = (len == 0.0f) ? 0.0f : (SQRT2_F * env * inv);

    float s1, c1;
    sincospif(len, &s1, &c1);
    float out[8];
    float sm1 = 0.0f, sk = s1;
#pragma unroll
    for (int k = 0; k < 8; k++) {
        out[k] = sk * coef;
        float nx = 2.0f * c1 * sk - sm1;
        sm1 = sk; sk = nx;
    }
    *(float4*)&g_radial[e * 8]     = make_float4(out[0], out[1], out[2], out[3]);
    *(float4*)&g_radial[e * 8 + 4] = make_float4(out[4], out[5], out[6], out[7]);
}

// ---------------------------------------------------------------------------
// FUSED radial-MLP + edge message + scatter.
// MLP identical to R12/R14 (tf32 p1, bf16 k16 p2/p3). Mix never touches
// gmem: staged through 2KB smem per CTA, then each warp's 32 lanes run the
// edge phase for its 16 edges (lane e = lane&15; halves split the 9 reds).
// ---------------------------------------------------------------------------
__global__ __launch_bounds__(128)
void k_mix_edge(const float* __restrict__ W1, const float* __restrict__ W2,
                const float* __restrict__ W3,
                const int* __restrict__ snd, const int* __restrict__ rcv,
                const float* __restrict__ Wds, const float* __restrict__ Wdv,
                int ne, int ntiles) {
    __shared__ ull sB1h[8 * 32],  sB1l[8 * 32];    // W1 tf32 packs
    __shared__ ull sB2h[32 * 32], sB2l[32 * 32];   // W2 bf16 packs
    __shared__ ull sB3h[4 * 32],  sB3l[4 * 32];    // W3 bf16 packs
    __shared__ float smix[4][16 * 8];              // per-warp mix staging

    int tid = threadIdx.x;

    for (int idx = tid; idx < 256; idx += 128) {
        int j = idx >> 5, l = idx & 31;
        float w0 = W1[(l & 3) * 64 + 8 * j + (l >> 2)] * INV_SQRT8;
        float w1 = W1[((l & 3) + 4) * 64 + 8 * j + (l >> 2)] * INV_SQRT8;
        uint32_t h0, l0, h1, l1;
        tf32split(w0, h0, l0); tf32split(w1, h1, l1);
        sB1h[idx] = ((ull)h1 << 32) | h0;
        sB1l[idx] = ((ull)l1 << 32) | l0;
    }
    for (int idx = tid; idx < 1024; idx += 128) {
        int t = idx >> 5, l = idx & 31;
        int kk = t >> 3, j = t & 7;
        int g = l >> 2, t4 = l & 3;
        int col = 8 * j + g;
        int r0 = 16 * kk + 2 * t4;
        float w00 = W2[(r0 + 0) * 64 + col] * 0.125f;
        float w01 = W2[(r0 + 1) * 64 + col] * 0.125f;
        float w10 = W2[(r0 + 8) * 64 + col] * 0.125f;
        float w11 = W2[(r0 + 9) * 64 + col] * 0.125f;
        uint32_t b0h, b0l, b1h, b1l;
        bfsplit2(w00, w01, b0h, b0l);
        bfsplit2(w10, w11, b1h, b1l);
        sB2h[idx] = ((ull)b1h << 32) | b0h;
        sB2l[idx] = ((ull)b1l << 32) | b0l;
    }
    for (int idx = tid; idx < 128; idx += 128) {
        int kk = idx >> 5, l = idx & 31;
        int g = l >> 2, t4 = l & 3;
        int r0 = 16 * kk + 2 * t4;
        float w00 = W3[(r0 + 0) * 8 + g] * 0.125f;
        float w01 = W3[(r0 + 1) * 8 + g] * 0.125f;
        float w10 = W3[(r0 + 8) * 8 + g] * 0.125f;
        float w11 = W3[(r0 + 9) * 8 + g] * 0.125f;
        uint32_t b0h, b0l, b1h, b1l;
        bfsplit2(w00, w01, b0h, b0l);
        bfsplit2(w10, w11, b1h, b1l);
        sB3h[idx] = ((ull)b1h << 32) | b0h;
        sB3l[idx] = ((ull)b1l << 32) | b0l;
    }
    __syncthreads();

    int w    = tid >> 5;
    int lane = tid & 31;
    int g    = lane >> 2;
    int t4   = lane & 3;
    float* sm = smix[w];

    for (int tile = blockIdx.x; tile < ntiles; tile += gridDim.x) {
        int base = tile * 64 + w * 16;
        int eg  = base + g;      if (eg  >= ne) eg  = ne - 1;
        int eg8 = base + g + 8;  if (eg8 >= ne) eg8 = ne - 1;

        // ===== phase 1 (tf32): h1 = swish(radial @ W1s) =====
        uint32_t ah[4], al[4];
        {
            float r0 = g_radial[eg  * 8 + t4];
            float r1 = g_radial[eg8 * 8 + t4];
            float r2 = g_radial[eg  * 8 + t4 + 4];
            float r3 = g_radial[eg8 * 8 + t4 + 4];
            tf32split(r0, ah[0], al[0]);
            tf32split(r1, ah[1], al[1]);
            tf32split(r2, ah[2], al[2]);
            tf32split(r3, ah[3], al[3]);
        }
        float hj[8][4];
#pragma unroll
        for (int j = 0; j < 8; j++) {
            float D[4] = {0.f, 0.f, 0.f, 0.f};
            ull bh = sB1h[j * 32 + lane];
            ull bl = sB1l[j * 32 + lane];
            uint32_t bh0 = (uint32_t)bh, bh1 = (uint32_t)(bh >> 32);
            uint32_t bl0 = (uint32_t)bl, bl1 = (uint32_t)(bl >> 32);
            mma8(D, ah, bh0, bh1);
            mma8(D, al, bh0, bh1);
            mma8(D, ah, bl0, bl1);
            hj[j][0] = swishf(D[0]);
            hj[j][1] = swishf(D[1]);
            hj[j][2] = swishf(D[2]);
            hj[j][3] = swishf(D[3]);
        }

        // ===== phase 2 (bf16 k16): h2 = swish(h1 @ W2s) =====
        float D2[8][4];
#pragma unroll
        for (int j = 0; j < 8; j++)
#pragma unroll
            for (int q = 0; q < 4; q++) D2[j][q] = 0.f;

#pragma unroll
        for (int kk = 0; kk < 4; kk++) {
            uint32_t a2h[4], a2l[4];
            bfsplit2(hj[2 * kk][0],     hj[2 * kk][1],     a2h[0], a2l[0]);
            bfsplit2(hj[2 * kk][2],     hj[2 * kk][3],     a2h[1], a2l[1]);
            bfsplit2(hj[2 * kk + 1][0], hj[2 * kk + 1][1], a2h[2], a2l[2]);
            bfsplit2(hj[2 * kk + 1][2], hj[2 * kk + 1][3], a2h[3], a2l[3]);
#pragma unroll
            for (int j = 0; j < 8; j++) {
                ull bh = sB2h[(kk * 8 + j) * 32 + lane];
                ull bl = sB2l[(kk * 8 + j) * 32 + lane];
                uint32_t bh0 = (uint32_t)bh, bh1 = (uint32_t)(bh >> 32);
                uint32_t bl0 = (uint32_t)bl, bl1 = (uint32_t)(bl >> 32);
                mma16(D2[j], a2h, bh0, bh1);
                mma16(D2[j], a2l, bh0, bh1);
                mma16(D2[j], a2h, bl0, bl1);
            }
        }
        float hj2[8][4];
#pragma unroll
        for (int j = 0; j < 8; j++) {
            hj2[j][0] = swishf(D2[j][0]);
            hj2[j][1] = swishf(D2[j][1]);
            hj2[j][2] = swishf(D2[j][2]);
            hj2[j][3] = swishf(D2[j][3]);
        }

        // ===== phase 3 (bf16 k16): mix = h2 @ W3s (N=8) =====
        float D3a[4] = {0.f, 0.f, 0.f, 0.f};
        float D3b[4] = {0.f, 0.f, 0.f, 0.f};
#pragma unroll
        for (int kk = 0; kk < 4; kk++) {
            uint32_t a3h[4], a3l[4];
            bfsplit2(hj2[2 * kk][0],     hj2[2 * kk][1],     a3h[0], a3l[0]);
            bfsplit2(hj2[2 * kk][2],     hj2[2 * kk][3],     a3h[1], a3l[1]);
            bfsplit2(hj2[2 * kk + 1][0], hj2[2 * kk + 1][1], a3h[2], a3l[2]);
            bfsplit2(hj2[2 * kk + 1][2], hj2[2 * kk + 1][3], a3h[3], a3l[3]);
            ull bh = sB3h[kk * 32 + lane];
            ull bl = sB3l[kk * 32 + lane];
            uint32_t bh0 = (uint32_t)bh, bh1 = (uint32_t)(bh >> 32);
            uint32_t bl0 = (uint32_t)bl, bl1 = (uint32_t)(bl >> 32);
            float* Dc = (kk & 1) ? D3b : D3a;
            mma16(Dc, a3h, bh0, bh1);
            mma16(Dc, a3l, bh0, bh1);
            mma16(Dc, a3h, bl0, bl1);
        }

        // ===== stage mix tile in smem (no gmem round trip) =====
        sm[g * 8 + 2 * t4]           = D3a[0] + D3b[0];
        sm[g * 8 + 2 * t4 + 1]       = D3a[1] + D3b[1];
        sm[(g + 8) * 8 + 2 * t4]     = D3a[2] + D3b[2];
        sm[(g + 8) * 8 + 2 * t4 + 1] = D3a[3] + D3b[3];
        __syncwarp();

        // ===== fused edge phase: lane e = lane&15, halves split the reds ====
        {
            int eidx = lane & 15;
            int half = lane >> 4;
            int e = base + eidx;
            if (e < ne) {
                int s = snd[e], r = rcv[e];
                float4 nh = *(const float4*)&g_nhat[e * 4];
                float nx = nh.x, ny = nh.y, nz = nh.z;
                float4 q0 = *(const float4*)&sm[eidx * 8];
                float4 q1 = *(const float4*)&sm[eidx * 8 + 4];

                float4 p0 = *(const float4*)&g_vus[s * 8];
                float4 p1 = *(const float4*)&g_vus[s * 8 + 4];
                float se = p0.w;
                float v0x = p0.x, v0y = p0.y, v0z = p0.z;
                float v1x = p1.x, v1y = p1.y, v1z = p1.z;

                float d0 = v0x * nx + v0y * ny + v0z * nz;
                float d1 = v1x * nx + v1y * ny + v1z * nz;

                const float third = 1.0f / 3.0f;
                float c0 = C121_F * q1.y;
                float c1 = C121_F * q1.z;
                float cb = SQRT3_F * se * q1.w;

                float ms0 = se * q0.x;
                float ms1 = d0 * q0.y;
                float ms2 = d1 * q0.z;
                float* basep = &g_agg[r * 12];

                if (half == 0) {
                    float sd[3];
#pragma unroll
                    for (int k = 0; k < 3; k++)
                        sd[k] = (ms0 * Wds[k] + ms1 * Wds[3 + k] +
                                 ms2 * Wds[6 + k]) * INV_SQRT3;
                    // vd[0][0] (k=0, c=x)
                    float r0 = v0x * q0.w;
                    float r1 = v1x * q1.x;
                    float r2 = c0 * (d0 * nx - v0x * third);
                    float r3 = c1 * (d1 * nx - v1x * third);
                    float r4 = cb * nx;
                    float vd00 = (r0 * Wdv[0] + r1 * Wdv[2] + r2 * Wdv[4] +
                                  r3 * Wdv[6] + r4 * Wdv[8]) * INV_SQRT5;
                    asm volatile("red.global.add.v4.f32 [%0], {%1, %2, %3, %4};"
                                 :: "l"(basep), "f"(sd[0]), "f"(sd[1]),
                                    "f"(sd[2]), "f"(vd00) : "memory");
                } else {
                    // vd[0][y,z], vd[1][x,y,z]
                    float vdv[5];
                    {   // k=0: c=y,z
                        float ry0 = v0y * q0.w, ry1 = v1y * q1.x;
                        float ry2 = c0 * (d0 * ny - v0y * third);
                        float ry3 = c1 * (d1 * ny - v1y * third);
                        float ry4 = cb * ny;
                        vdv[0] = (ry0 * Wdv[0] + ry1 * Wdv[2] + ry2 * Wdv[4] +
                                  ry3 * Wdv[6] + ry4 * Wdv[8]) * INV_SQRT5;
                        float rz0 = v0z * q0.w, rz1 = v1z * q1.x;
                        float rz2 = c0 * (d0 * nz - v0z * third);
                        float rz3 = c1 * (d1 * nz - v1z * third);
                        float rz4 = cb * nz;
                        vdv[1] = (rz0 * Wdv[0] + rz1 * Wdv[2] + rz2 * Wdv[4] +
                                  rz3 * Wdv[6] + rz4 * Wdv[8]) * INV_SQRT5;
                    }
#pragma unroll
                    for (int c = 0; c < 3; c++) {
                        float n_c = (c == 0) ? nx : ((c == 1) ? ny : nz);
                        float v0c = (c == 0) ? v0x : ((c == 1) ? v0y : v0z);
                        float v1c = (c == 0) ? v1x : ((c == 1) ? v1y : v1z);
                        float r0 = v0c * q0.w;
                        float r1 = v1c * q1.x;
                        float r2 = c0 * (d0 * n_c - v0c * third);
                        float r3 = c1 * (d1 * n_c - v1c * third);
                        float r4 = cb * n_c;
                        vdv[2 + c] = (r0 * Wdv[1] + r1 * Wdv[3] + r2 * Wdv[5] +
                                      r3 * Wdv[7] + r4 * Wdv[9]) * INV_SQRT5;
                    }
                    asm volatile("red.global.add.v4.f32 [%0], {%1, %2, %3, %4};"
                                 :: "l"(basep + 4), "f"(vdv[0]), "f"(vdv[1]),
                                    "f"(vdv[2]), "f"(vdv[3]) : "memory");
                    asm volatile("red.global.add.f32 [%0], %1;"
                                 :: "l"(basep + 8), "f"(vdv[4]) : "memory");
                }
            }
        }
        __syncwarp();
    }
}

// ---------------------------------------------------------------------------
// node pre: su/vu (packed record) from current s/v, zero agg (12 floats)
// ---------------------------------------------------------------------------
__global__ void k_node_pre(const float* __restrict__ Wus,
                           const float* __restrict__ Wuv, int nn) {
    int n = blockIdx.x * blockDim.x + threadIdx.x;
    if (n >= nn) return;
    float s = g_s[n];
    float su = s * Wus[0];
    float w00 = Wuv[0], w01 = Wuv[1], w10 = Wuv[2], w11 = Wuv[3];
    float vu0[3], vu1[3];
#pragma unroll
    for (int c = 0; c < 3; c++) {
        float a = g_v[n * 6 + c], b = g_v[n * 6 + 3 + c];
        vu0[c] = (a * w00 + b * w10) * INV_SQRT2;
        vu1[c] = (a * w01 + b * w11) * INV_SQRT2;
    }
    *(float4*)&g_vus[n * 8]     = make_float4(vu0[0], vu0[1], vu0[2], su);
    *(float4*)&g_vus[n * 8 + 4] = make_float4(vu1[0], vu1[1], vu1[2], 0.0f);
    float4 z = make_float4(0.f, 0.f, 0.f, 0.f);
#pragma unroll
    for (int i = 0; i < 3; i++) *(float4*)&g_agg[n * 12 + 4 * i] = z;
}

// ---------------------------------------------------------------------------
// node post: residual, gates, update s/v (agg already contracted)
// ---------------------------------------------------------------------------
__global__ void k_node_post(const float* __restrict__ Wss,
                            const float* __restrict__ Wsv,
                            float* __restrict__ out, int write_out, int nn) {
    int n = blockIdx.x * blockDim.x + threadIdx.x;
    if (n >= nn) return;
    float s = g_s[n];
    float v[6];
#pragma unroll
    for (int i = 0; i < 6; i++) v[i] = g_v[n * 6 + i];
    float agg[9];
#pragma unroll
    for (int i = 0; i < 9; i++) agg[i] = g_agg[n * 12 + i];

    float st[3];
#pragma unroll
    for (int k = 0; k < 3; k++) st[k] = agg[k] + s * Wss[k];

    float vt[6];
#pragma unroll
    for (int k = 0; k < 2; k++) {
#pragma unroll
        for (int c = 0; c < 3; c++) {
            float vsc = (v[c] * Wsv[0 * 2 + k] + v[3 + c] * Wsv[1 * 2 + k]) * INV_SQRT2;
            vt[k * 3 + c] = agg[3 + 3 * k + c] + vsc;
        }
    }
    float ns = swish_exact(st[0]);
    float g1 = swish_exact(st[1]);
    float g2 = swish_exact(st[2]);
    g_s[n] = ns;
#pragma unroll
    for (int c = 0; c < 3; c++) {
        float nv0 = vt[c] * g1;
        float nv1 = vt[3 + c] * g2;
        g_v[n * 6 + c]     = nv0;
        g_v[n * 6 + 3 + c] = nv1;
        if (write_out) out[n * 3 + c] = nv0;
    }
}

// ---------------------------------------------------------------------------
// launch
// ---------------------------------------------------------------------------
extern "C" void kernel_launch(void* const* d_in, const int* in_sizes, int n_in,
                              void* d_out, int out_size) {
    const float* pos = (const float*)d_in[0];
    const float* nf  = (const float*)d_in[1];
    const int* snd   = (const int*)d_in[2];
    const int* rcv   = (const int*)d_in[3];
    const float* Wss = (const float*)d_in[4];
    const float* Wsv = (const float*)d_in[5];
    const float* Wus = (const float*)d_in[6];
    const float* Wuv = (const float*)d_in[7];
    const float* W1  = (const float*)d_in[8];
    const float* W2  = (const float*)d_in[9];
    const float* W3  = (const float*)d_in[10];
    const float* Wds = (const float*)d_in[11];
    const float* Wdv = (const float*)d_in[12];
    float* out = (float*)d_out;

    int ne = in_sizes[2];
    int nn = in_sizes[0] / 3;

    int nb_n = (nn + 255) / 256;
    int nb_e = (ne + 255) / 256;
    int ntiles = (ne + 63) / 64;
    int nb_t = ntiles < 888 ? ntiles : 888;

    k_init<<<nb_n, 256>>>(nf, nn);
    k_geom<<<nb_e, 256>>>(pos, snd, rcv, ne);

    for (int l = 0; l < 3; l++) {
        k_node_pre<<<nb_n, 256>>>(Wus + l * 1, Wuv + l * 4, nn);
        k_mix_edge<<<nb_t, 128>>>(W1 + l * 512, W2 + l * 4096, W3 + l * 512,
                                  snd, rcv, Wds + l * 9, Wdv + l * 10,
                                  ne, ntiles);
        k_node_post<<<nb_n, 256>>>(Wss + l * 3, Wsv + l * 4,
                                   out, (l == 2) ? 1 : 0, nn);
    }
}